// round 16
// baseline (speedup 1.0000x reference)
#include <cuda_runtime.h>
#include <cuda_fp16.h>
#include <math.h>
#include <cstdint>

#define HD 2048
#define ID 1408
#define NE 16
#define TK 4
#define NT 1024
#define SID 2816
#define RSCALE 2.5f

// ---------------- scratch ----------------
__device__ int    d_cnt[NE];
__device__ int    d_tok[NE * NT];
__device__ float  d_wt [NE * NT];
__device__ __half w_d16[NE * HD * ID];   // wd converted via gemm1 z-fill
__device__ __half sw_d16[HD * SID];      // sd converted in prologue
__device__ __half x16  [NT * HD];        // x converted in prologue
__device__ __half h_r16[NE * NT * ID];
__device__ __half h_s16[NT * SID];

// ---------------- PTX helpers ----------------
__device__ __forceinline__ uint32_t smem_u32(const void* p) {
    uint32_t a;
    asm("{ .reg .u64 t; cvta.to.shared.u64 t, %1; cvt.u32.u64 %0, t; }"
        : "=r"(a) : "l"(p));
    return a;
}
#define CP_ASYNC(dst, src, sz) \
    asm volatile("cp.async.cg.shared.global [%0], [%1], 16, %2;" \
                 :: "r"(dst), "l"(src), "r"(sz) : "memory")
#define CP_COMMIT() asm volatile("cp.async.commit_group;" ::: "memory")
#define CP_WAIT(n)  asm volatile("cp.async.wait_group %0;" :: "n"(n) : "memory")

__device__ __forceinline__ void mma16(float* c, const uint32_t* a, const uint32_t* b) {
    asm volatile(
        "mma.sync.aligned.m16n8k16.row.col.f32.f16.f16.f32 "
        "{%0,%1,%2,%3}, {%4,%5,%6,%7}, {%8,%9}, {%0,%1,%2,%3};"
        : "+f"(c[0]), "+f"(c[1]), "+f"(c[2]), "+f"(c[3])
        : "r"(a[0]), "r"(a[1]), "r"(a[2]), "r"(a[3]), "r"(b[0]), "r"(b[1]));
}
__device__ __forceinline__ void red_add2(float* o, float v0, float v1) {
    asm volatile("red.global.add.v2.f32 [%0], {%1, %2};"
                 :: "l"(o), "f"(v0), "f"(v1) : "memory");
}
__device__ __forceinline__ float silu(float g) { return g / (1.f + __expf(-g)); }
__device__ __forceinline__ uint32_t h2u(__half2 h) {
    uint32_t u; *(__half2*)&u = h; return u;
}
__device__ __forceinline__ uint32_t pk(float a, float b) {
    return h2u(__floats2half2_rn(a, b));
}

// smem rows: 64B data (32 fp16, permuted) + 32B pad = 96B (12 uint2)
#define ROWB 96
#define ROWU2 12

// ---------------- init ----------------
__global__ void init_kernel() {
    if (threadIdx.x < NE) d_cnt[threadIdx.x] = 0;
}

// ---------------- conversion unit -------------------------------------------
#define U_W ((size_t)NE * ID * HD / 16)
#define U_S ((size_t)SID * HD / 16)
#define U_X ((size_t)NT * HD / 16)
#define U_PRO (U_S + U_X)                       // sd + x only
#define CONV_BLOCKS ((int)(U_PRO / 256))
#define ZERO_BLOCKS ((NT * HD) / 1024)
#define PRO_BLOCKS  (NT + ZERO_BLOCKS + CONV_BLOCKS)
#define WD_ZSLICES  ((int)(U_W / 256 / 176))

__device__ __forceinline__ void conv_unit(const float4* __restrict__ s,
                                          uint4* __restrict__ d, size_t t) {
    float4 f0 = s[4 * t], f1 = s[4 * t + 1], f2 = s[4 * t + 2], f3 = s[4 * t + 3];
    d[2 * t]     = make_uint4(pk(f0.x, f0.y), pk(f2.x, f2.y),
                              pk(f0.z, f0.w), pk(f2.z, f2.w));
    d[2 * t + 1] = make_uint4(pk(f1.x, f1.y), pk(f3.x, f3.y),
                              pk(f1.z, f1.w), pk(f3.z, f3.w));
}

// ---------------- fused prologue: gate | zero_out | conv(sd, x) -------------
__device__ void gate_block(int t, const float* __restrict__ x,
                           const float* __restrict__ gw,
                           const float* __restrict__ gb) {
    __shared__ float s_sc[NE];
    const int wid = threadIdx.x >> 5, lane = threadIdx.x & 31;
    const float4* xr = (const float4*)(x + (size_t)t * HD);
    #pragma unroll
    for (int eo = 0; eo < 2; eo++) {
        const int e = wid + eo * 8;
        const float4* wr = (const float4*)(gw + (size_t)e * HD);
        float acc = 0.f;
        #pragma unroll 4
        for (int k = lane; k < HD / 4; k += 32) {
            float4 a = xr[k], b = wr[k];
            acc += a.x * b.x + a.y * b.y + a.z * b.z + a.w * b.w;
        }
        #pragma unroll
        for (int o = 16; o; o >>= 1) acc += __shfl_xor_sync(0xffffffffu, acc, o);
        if (lane == 0) s_sc[e] = 1.f / (1.f + expf(-acc)) + gb[e];
    }
    __syncthreads();
    if (threadIdx.x != 0) return;

    float sc[NE];
    #pragma unroll
    for (int e = 0; e < NE; e++) sc[e] = s_sc[e];
    float gs[4];
    #pragma unroll
    for (int g = 0; g < 4; g++) {
        float m = sc[g * 4];
        #pragma unroll
        for (int j = 1; j < 4; j++) m = fmaxf(m, sc[g * 4 + j]);
        gs[g] = m;
    }
    int g0 = 0;
    for (int g = 1; g < 4; g++) if (gs[g] > gs[g0]) g0 = g;
    int g1 = -1;
    for (int g = 0; g < 4; g++) {
        if (g == g0) continue;
        if (g1 < 0 || gs[g] > gs[g1]) g1 = g;
    }
    float masked[NE];
    #pragma unroll
    for (int e = 0; e < NE; e++) {
        int g = e >> 2;
        masked[e] = (g == g0 || g == g1) ? sc[e] : 0.f;
    }
    int idx[TK]; float w[TK]; bool used[NE];
    #pragma unroll
    for (int e = 0; e < NE; e++) used[e] = false;
    float wsum = 0.f;
    for (int k = 0; k < TK; k++) {
        int best = -1;
        for (int e = 0; e < NE; e++) {
            if (used[e]) continue;
            if (best < 0 || masked[e] > masked[best]) best = e;
        }
        used[best] = true;
        idx[k] = best; w[k] = masked[best]; wsum += masked[best];
    }
    const float inv = 1.f / (wsum + 1e-6f);
    for (int k = 0; k < TK; k++) {
        int e = idx[k];
        int pos = atomicAdd(&d_cnt[e], 1);
        d_tok[e * NT + pos] = t;
        d_wt [e * NT + pos] = w[k] * inv * RSCALE;
    }
}

__global__ void prologue(const float* x, const float* gate_w, const float* gate_b,
                         float4* out,
                         const float4* sd, uint4* osd, uint4* oxx) {
    const int b = blockIdx.x;
    if (b < NT) { gate_block(b, x, gate_w, gate_b); return; }
    if (b < NT + ZERO_BLOCKS) {
        out[(size_t)(b - NT) * 256 + threadIdx.x] = make_float4(0.f, 0.f, 0.f, 0.f);
        return;
    }
    size_t u = (size_t)(b - NT - ZERO_BLOCKS) * 256 + threadIdx.x;
    if (u < U_S) { conv_unit(sd, osd, u); return; }
    u -= U_S;
    conv_unit((const float4*)x, oxx, u);
}

// ---------------- GEMM1: A fp16 cp.async, weights fp32 LDG->cvt->STS -------
// Tile 128M x 64N dual, Kc=32, 4-stage. Consumer identical to R15.
#define G1_STAGE 24576
#define G1_SMEM  (512 + 4 * G1_STAGE)
__global__ void __launch_bounds__(256, 2)
gemm1_h(const __half* __restrict__ X,
        const float* __restrict__ Wg_r, const float* __restrict__ Wu_r,
        const float* __restrict__ Wg_s, const float* __restrict__ Wu_s,
        __half* __restrict__ Hr, __half* __restrict__ Hs,
        const float4* __restrict__ Wd32, uint4* __restrict__ oWd) {
    const int e = blockIdx.z;
    if (e >= NE + 2) {
        const size_t cid = ((size_t)(e - NE - 2) * 8 + blockIdx.y) * 22 + blockIdx.x;
        conv_unit(Wd32, oWd, cid * 256 + threadIdx.x);
        return;
    }
    const bool SH = (e >= NE);
    int M, ldH, n0;
    const float *Wg, *Wu; __half* Ho;
    if (SH) {
        M = NT; ldH = SID;
        Wg = Wg_s; Wu = Wu_s; Ho = Hs;
        n0 = ((int)blockIdx.x + (e == NE + 1 ? 22 : 0)) * 64;
    } else {
        M = d_cnt[e]; ldH = ID;
        Wg = Wg_r + (size_t)e * ID * HD;
        Wu = Wu_r + (size_t)e * ID * HD;
        Ho = Hr + (size_t)e * NT * ID;
        n0 = (int)blockIdx.x * 64;
    }
    const int m0 = blockIdx.y * 128;
    if (m0 >= M) return;
    const int K = HD;

    extern __shared__ char smem[];
    int* s_tok = (int*)smem;
    const int tid = threadIdx.x, lane = tid & 31, wid = tid >> 5;
    const int wr = wid >> 2, wc = wid & 3;
    if (!SH && tid < 128) s_tok[tid] = (m0 + tid < M) ? d_tok[e * NT + m0 + tid] : 0;
    __syncthreads();

    // A loader: cp.async fp16 from x16 (unchanged)
    const int rA = tid >> 1, sA = (tid & 1) * 2;
    const bool aok = (m0 + rA) < M;
    const int ar = SH ? (aok ? m0 + rA : 0) : (aok ? s_tok[rA] : 0);
    const char* Ap = (const char*)(X + (size_t)ar * K);
    const uint32_t sb = smem_u32(smem) + 512;
    const uint32_t dA = sb + rA * ROWB + sA * 16;
    const uint32_t szA = aok ? 16u : 0u;

    // Weight loader: fp32 LDG -> pair-permuted fp16 -> STS
    // threads 0-127: G (row=t>>1, grp=t&1); 128-255: U
    const bool isG = tid < 128;
    const int tw = isG ? tid : tid - 128;
    const int rW = tw >> 1, gW = tw & 1;
    const float4* Wsrc = (const float4*)((isG ? Wg : Wu) + (size_t)(n0 + rW) * K) + gW * 4;
    uint32_t* dW = (uint32_t*)(smem + 512 + (isG ? 12288 : 18432) + rW * ROWB + gW * 32);

    const int C = K >> 5;
    float4 v0, v1, v2, v3;
    auto wld = [&](int c) {
        v0 = Wsrc[c * 8];     v1 = Wsrc[c * 8 + 1];
        v2 = Wsrc[c * 8 + 2]; v3 = Wsrc[c * 8 + 3];
    };
    auto wst = [&](int buf) {
        uint32_t* d = dW + buf * (G1_STAGE / 4);
        *(uint4*)d       = make_uint4(pk(v0.x, v0.y), pk(v2.x, v2.y),
                                      pk(v0.z, v0.w), pk(v2.z, v2.w));
        *(uint4*)(d + 4) = make_uint4(pk(v1.x, v1.y), pk(v3.x, v3.y),
                                      pk(v1.z, v1.w), pk(v3.z, v3.w));
    };
    auto loadA = [&](int c, int buf) {
        const int off = c * 64;
        const uint32_t b = buf * G1_STAGE;
        CP_ASYNC(dA + b,      Ap + off + sA * 16,      szA);
        CP_ASYNC(dA + b + 16, Ap + off + sA * 16 + 16, szA);
    };

    float cg[4][2][4] = {}, cu[4][2][4] = {};
    // prologue: weights 0..2 staged+stored, 3 staged; A groups 0..2 committed
    wld(0); wst(0); wld(1); wst(1); wld(2); wst(2);
    if (C > 3) wld(3);
    #pragma unroll
    for (int s = 0; s < 3; s++) { if (s < C) loadA(s, s); CP_COMMIT(); }

    const int l4 = lane >> 2, lm = lane & 3;
    const int a_off = (wr * 64 + l4) * ROWU2 + lm;
    const int g_off = 1536 + (wc * 16 + l4) * ROWU2 + lm;
    #pragma unroll 1
    for (int c = 0; c < C; c++) {
        CP_WAIT(2);
        __syncthreads();
        const int nc = c + 3;
        if (nc < C) {
            wst(nc & 3);
            if (c + 4 < C) wld(c + 4);
            loadA(nc, nc & 3);
        }
        CP_COMMIT();
        const uint2* S = (const uint2*)(smem + 512 + (c & 3) * G1_STAGE);
        #pragma unroll
        for (int ks = 0; ks < 2; ks++) {
            uint32_t a[4][4];
            #pragma unroll
            for (int mi = 0; mi < 4; mi++) {
                const uint2 p = S[a_off + mi * (16 * ROWU2) + ks * 4];
                const uint2 q = S[a_off + mi * (16 * ROWU2) + 8 * ROWU2 + ks * 4];
                a[mi][0] = p.x; a[mi][1] = q.x; a[mi][2] = p.y; a[mi][3] = q.y;
            }
            #pragma unroll
            for (int ni = 0; ni < 2; ni++) {
                const uint2 vg = S[g_off + ni * (8 * ROWU2) + ks * 4];
                const uint2 vu = S[g_off + 768 + ni * (8 * ROWU2) + ks * 4];
                uint32_t bg[2] = { vg.x, vg.y };
                uint32_t bu[2] = { vu.x, vu.y };
                #pragma unroll
                for (int mi = 0; mi < 4; mi++) {
                    mma16(cg[mi][ni], a[mi], bg);
                    mma16(cu[mi][ni], a[mi], bu);
                }
            }
        }
    }
    #pragma unroll
    for (int mi = 0; mi < 4; mi++)
        #pragma unroll
        for (int h = 0; h < 2; h++) {
            const int r = m0 + wr * 64 + mi * 16 + l4 + h * 8;
            if (r >= M) continue;
            const float v0e = silu(cg[mi][0][2 * h + 0]) * cu[mi][0][2 * h + 0];
            const float v1e = silu(cg[mi][0][2 * h + 1]) * cu[mi][0][2 * h + 1];
            const float v2e = silu(cg[mi][1][2 * h + 0]) * cu[mi][1][2 * h + 0];
            const float v3e = silu(cg[mi][1][2 * h + 1]) * cu[mi][1][2 * h + 1];
            uint2 val = { pk(v0e, v1e), pk(v2e, v3e) };
            ((uint2*)(Ho + (size_t)r * ldH + n0 + wc * 16))[lm] = val;
        }
}

// ---------------- GEMM2 fp16 (R15, unchanged): 128M x 64N, 3 CTAs/SM -------
#define G2_STAGE 18432
#define G2_SMEM  (1024 + 4 * G2_STAGE)
__global__ void __launch_bounds__(256, 3)
gemm2_h(const __half* __restrict__ Hr, const __half* __restrict__ Wd_r,
        const __half* __restrict__ Hs, const __half* __restrict__ Wd_s,
        float* __restrict__ Out) {
    const int zz = blockIdx.z;
    const bool SH = (zz == 0);
    const int e = SH ? 0 : zz - 1;
    int M, K;
    const __half *Hin, *Wd;
    if (SH) {
        M = NT; K = SID; Hin = Hs; Wd = Wd_s;
    } else {
        M = d_cnt[e]; K = ID;
        Hin = Hr + (size_t)e * NT * ID;
        Wd  = Wd_r + (size_t)e * HD * ID;
    }
    const int m0 = blockIdx.y * 128;
    if (m0 >= M) return;
    const int n0 = blockIdx.x * 64;

    extern __shared__ char smem[];
    int*   s_tok = (int*)smem;
    float* s_wt  = (float*)(smem + 512);
    const int tid = threadIdx.x, lane = tid & 31, wid = tid >> 5;
    const int wr = wid >> 2, wc = wid & 3;
    if (tid < 128) {
        const bool ok = m0 + tid < M;
        if (SH) { s_tok[tid] = ok ? m0 + tid : 0; s_wt[tid] = 1.f; }
        else {
            s_tok[tid] = ok ? d_tok[e * NT + m0 + tid] : 0;
            s_wt [tid] = ok ? d_wt [e * NT + m0 + tid] : 0.f;
        }
    }
    __syncthreads();

    const int rA = tid >> 1, sA = (tid & 1) * 2;
    const int rB = tid >> 2, sB = tid & 3;
    const bool aok = (m0 + rA) < M;
    const char* Ap = (const char*)(Hin + (size_t)(aok ? m0 + rA : 0) * K);
    const char* Bp = (const char*)(Wd + (size_t)(n0 + rB) * K);
    const uint32_t sb = smem_u32(smem) + 1024;
    const uint32_t dA = sb + rA * ROWB + sA * 16;
    const uint32_t dB = sb + 12288 + rB * ROWB + sB * 16;
    const uint32_t szA = aok ? 16u : 0u;

    const int C = K >> 5;
    auto load = [&](int c, int buf) {
        const int off = c * 64;
        const uint32_t b = buf * G2_STAGE;
        CP_ASYNC(dA + b,      Ap + off + sA * 16,      szA);
        CP_ASYNC(dA + b + 16, Ap + off + sA * 16 + 16, szA);
        CP_ASYNC(dB + b,      Bp + off + sB * 16, 16);
    };

    float acc[4][2][4] = {};
    #pragma unroll
    for (int s = 0; s < 3; s++) { if (s < C) load(s, s); CP_COMMIT(); }

    const int l4 = lane >> 2, lm = lane & 3;
    const int a_off = (wr * 64 + l4) * ROWU2 + lm;
    const int b_off = 1536 + (wc * 16 + l4) * ROWU2 + lm;
    #pragma unroll 1
    for (int c = 0; c < C; c++) {
        CP_WAIT(2);
        __syncthreads();
        const int nc = c + 3;
        if (nc < C) load(nc, nc & 3);
        CP_COMMIT();
        const uint2* S = (const uint2*)(smem + 1024 + (c & 3) * G2_STAGE);
        #pragma unroll
        for (int ks = 0; ks < 2; ks++) {
            uint32_t a[4][4];
            #pragma unroll
            for (int mi = 0; mi < 4; mi++) {
                const uint2 p = S[a_off + mi * (16 * ROWU2) + ks * 4];
                const uint2 q = S[a_off + mi * (16 * ROWU2) + 8 * ROWU2 + ks * 4];
                a[mi][0] = p.x; a[mi][1] = q.x; a[mi][2] = p.y; a[mi][3] = q.y;
            }
            #pragma unroll
            for (int ni = 0; ni < 2; ni++) {
                const uint2 vb = S[b_off + ni * (8 * ROWU2) + ks * 4];
                uint32_t b[2] = { vb.x, vb.y };
                #pragma unroll
                for (int mi = 0; mi < 4; mi++)
                    mma16(acc[mi][ni], a[mi], b);
            }
        }
    }
    #pragma unroll
    for (int mi = 0; mi < 4; mi++) {
        const int rl0 = wr * 64 + mi * 16 + l4;
        #pragma unroll
        for (int ni = 0; ni < 2; ni++) {
            const int cc = n0 + wc * 16 + ni * 8 + 2 * lm;
            #pragma unroll
            for (int h = 0; h < 2; h++) {
                const int rl = rl0 + h * 8;
                if (m0 + rl >= M) continue;
                const float w = s_wt[rl];
                float* o = Out + (size_t)s_tok[rl] * HD + cc;
                red_add2(o, w * acc[mi][ni][2 * h + 0], w * acc[mi][ni][2 * h + 1]);
            }
        }
    }
}

// ---------------- launch ----------------
extern "C" void kernel_launch(void* const* d_in, const int* in_sizes, int n_in,
                              void* d_out, int out_size) {
    const float* x       = (const float*)d_in[0];
    const float* gate_w  = (const float*)d_in[1];
    const float* gate_b  = (const float*)d_in[2];
    const float* w_gate  = (const float*)d_in[3];
    const float* w_up    = (const float*)d_in[4];
    const float* w_down  = (const float*)d_in[5];
    const float* sw_gate = (const float*)d_in[6];
    const float* sw_up   = (const float*)d_in[7];
    const float* sw_down = (const float*)d_in[8];
    float* out = (float*)d_out;

    __half *wd16, *sd16, *xh, *hr, *hs;
    cudaGetSymbolAddress((void**)&wd16, w_d16);
    cudaGetSymbolAddress((void**)&sd16, sw_d16);
    cudaGetSymbolAddress((void**)&xh,   x16);
    cudaGetSymbolAddress((void**)&hr,   h_r16);
    cudaGetSymbolAddress((void**)&hs,   h_s16);

    cudaFuncSetAttribute(gemm1_h, cudaFuncAttributeMaxDynamicSharedMemorySize, G1_SMEM);
    cudaFuncSetAttribute(gemm2_h, cudaFuncAttributeMaxDynamicSharedMemorySize, G2_SMEM);

    init_kernel<<<1, 32>>>();
    // fused: gate | zero out | conv(sw_down, x)
    prologue<<<PRO_BLOCKS, 256>>>(
        x, gate_w, gate_b, (float4*)out,
        (const float4*)sw_down, (uint4*)sd16, (uint4*)xh);

    // gate/up + silu (weights fp32 direct): z 0..15 routed, z 16/17 shared,
    // z 18.. w_down conversion fill
    gemm1_h<<<dim3(22, NT / 128, NE + 2 + WD_ZSLICES), 256, G1_SMEM>>>(
        xh, w_gate, w_up, sw_gate, sw_up, hr, hs,
        (const float4*)w_down, (uint4*)wd16);
    // down: z=0 shared (K=SID), z=1..16 routed (K=ID); v2 reductions
    gemm2_h<<<dim3(HD / 64, NT / 128, NE + 1), 256, G2_SMEM>>>(
        hr, wd16, hs, sd16, out);
}